// round 7
// baseline (speedup 1.0000x reference)
#include <cuda_runtime.h>
#include <cstdint>

#define BB 1024      // batch
#define DD 512       // feature dim
#define MM 256       // modes
#define THRESHV 1.0f
#define RB 8         // batch rows per scores-block

// ---------------------------------------------------------------------------
// Kernel 1: scores[b,m] = softmax_m( dot(x[b,:], W[m,:]) + bias[m] )
// 128 blocks x 256 threads; each block handles RB=8 batch rows so each W row
// (held in registers per k-step) is reused 8x. Softmax: warp w of the block
// normalizes row w (8 elements per lane + shuffle reductions).
// ---------------------------------------------------------------------------
__global__ __launch_bounds__(256)
void poly_scores_kernel(const float* __restrict__ x,
                        const float* __restrict__ W,
                        const float* __restrict__ bias,
                        float* __restrict__ scores)
{
    __shared__ float4 xs[RB * (DD / 4)];       // 8 rows * 512 floats = 16 KB
    __shared__ float  logits[RB][MM];          // 8 KB

    const int b0 = blockIdx.x * RB;
    const int t  = threadIdx.x;                // 0..255 == mode index

    // cooperatively load 8 x-rows (vectorized)
    const float4* x4 = reinterpret_cast<const float4*>(x + (size_t)b0 * DD);
    #pragma unroll
    for (int i = t; i < RB * (DD / 4); i += 256) xs[i] = x4[i];
    __syncthreads();

    float acc[RB];
    #pragma unroll
    for (int r = 0; r < RB; ++r) acc[r] = 0.0f;

    const float4* w4 = reinterpret_cast<const float4*>(W + (size_t)t * DD);
    #pragma unroll 4
    for (int k = 0; k < DD / 4; ++k) {
        float4 wv = w4[k];
        #pragma unroll
        for (int r = 0; r < RB; ++r) {
            float4 xv = xs[r * (DD / 4) + k];
            acc[r] = fmaf(wv.x, xv.x, acc[r]);
            acc[r] = fmaf(wv.y, xv.y, acc[r]);
            acc[r] = fmaf(wv.z, xv.z, acc[r]);
            acc[r] = fmaf(wv.w, xv.w, acc[r]);
        }
    }
    const float bv = bias[t];
    #pragma unroll
    for (int r = 0; r < RB; ++r) logits[r][t] = acc[r] + bv;
    __syncthreads();

    // softmax: warp w handles row w (256 elems, 8 per lane)
    const int w    = t >> 5;
    const int lane = t & 31;
    float v[8];
    float mx = -1e30f;
    #pragma unroll
    for (int j = 0; j < 8; ++j) { v[j] = logits[w][lane + 32 * j]; mx = fmaxf(mx, v[j]); }
    #pragma unroll
    for (int o = 16; o > 0; o >>= 1) mx = fmaxf(mx, __shfl_xor_sync(0xFFFFFFFFu, mx, o));
    float s = 0.0f;
    #pragma unroll
    for (int j = 0; j < 8; ++j) { v[j] = __expf(v[j] - mx); s += v[j]; }
    #pragma unroll
    for (int o = 16; o > 0; o >>= 1) s += __shfl_xor_sync(0xFFFFFFFFu, s, o);
    const float inv = 1.0f / s;

    float* srow = scores + (size_t)(b0 + w) * MM;
    #pragma unroll
    for (int j = 0; j < 8; ++j) srow[lane + 32 * j] = v[j] * inv;
}

// ---------------------------------------------------------------------------
// Kernel 2 (the HBM-bound one): per (b,d) stream over all 256 modes.
//   mem_new[m,b,d] = beta_m * mem[m,b,d] + x[b,d] - (mem[m,b,d] > 1)
//   mixed[b,d]    += (mem_new[m,b,d] - 1 > 0) * scores[b,m]
// 1024 blocks (one per b) x 128 threads (one float4 per thread over D=512).
// All global accesses are 128B-coalesced per warp; unroll 8 for MLP.
// ---------------------------------------------------------------------------
__global__ __launch_bounds__(128)
void poly_fused_kernel(const float* __restrict__ x,
                       const float* __restrict__ mem,
                       const float* __restrict__ scores,
                       float* __restrict__ mixed,
                       float* __restrict__ mem_new)
{
    __shared__ float s_sc[MM];

    const int b = blockIdx.x;
    const int t = threadIdx.x;                 // 0..127 (float4 lane over D)

    s_sc[t]       = scores[(size_t)b * MM + t];
    s_sc[t + 128] = scores[(size_t)b * MM + t + 128];
    __syncthreads();

    const size_t base = (size_t)b * (DD / 4) + t;   // in float4 units
    const float4 xv   = reinterpret_cast<const float4*>(x)[base];

    const float4* m4 = reinterpret_cast<const float4*>(mem);
    float4*       o4 = reinterpret_cast<float4*>(mem_new);

    float4 acc = make_float4(0.f, 0.f, 0.f, 0.f);
    const size_t stride = (size_t)(BB * DD / 4);    // 131072 float4 per mode

    #pragma unroll 8
    for (int m = 0; m < MM; ++m) {
        const size_t idx = base + (size_t)m * stride;
        const float4 mv  = __ldcs(m4 + idx);        // streaming: no reuse
        const float beta = (float)m / 257.0f;       // match jnp arange/257 exactly

        float4 mn;
        mn.x = fmaf(beta, mv.x, xv.x) - (mv.x > THRESHV ? 1.0f : 0.0f);
        mn.y = fmaf(beta, mv.y, xv.y) - (mv.y > THRESHV ? 1.0f : 0.0f);
        mn.z = fmaf(beta, mv.z, xv.z) - (mv.z > THRESHV ? 1.0f : 0.0f);
        mn.w = fmaf(beta, mv.w, xv.w) - (mv.w > THRESHV ? 1.0f : 0.0f);

        __stcs(o4 + idx, mn);

        const float sc = s_sc[m];
        acc.x += (mn.x - THRESHV > 0.0f) ? sc : 0.0f;
        acc.y += (mn.y - THRESHV > 0.0f) ? sc : 0.0f;
        acc.z += (mn.z - THRESHV > 0.0f) ? sc : 0.0f;
        acc.w += (mn.w - THRESHV > 0.0f) ? sc : 0.0f;
    }

    reinterpret_cast<float4*>(mixed)[base] = acc;
}

// ---------------------------------------------------------------------------
// Launch: outputs packed as [mixed (B*D) | mem_new (M*B*D) | scores (B*M)]
// ---------------------------------------------------------------------------
extern "C" void kernel_launch(void* const* d_in, const int* in_sizes, int n_in,
                              void* d_out, int out_size)
{
    const float* x    = (const float*)d_in[0];   // [B, D]
    const float* mem  = (const float*)d_in[1];   // [M, B, D]
    const float* W    = (const float*)d_in[2];   // [M, D]
    const float* bias = (const float*)d_in[3];   // [M]

    float* out      = (float*)d_out;
    float* mixed    = out;                                        // B*D
    float* mem_new  = out + (size_t)BB * DD;                      // M*B*D
    float* scores   = out + (size_t)BB * DD + (size_t)MM * BB * DD; // B*M

    poly_scores_kernel<<<BB / RB, 256>>>(x, W, bias, scores);
    poly_fused_kernel<<<BB, 128>>>(x, mem, scores, mixed, mem_new);
}

// round 8
// speedup vs baseline: 1.0670x; 1.0670x over previous
#include <cuda_runtime.h>
#include <cstdint>

#define BB 1024      // batch
#define DD 512       // feature dim
#define MM 256       // modes
#define THRESHV 1.0f
#define RB 8         // batch rows per scores-block
#define NCHUNK 4     // mode chunks for the fused kernel
#define MCH (MM / NCHUNK)   // 64 modes per chunk

// partial mixed accumulators, one slab per mode-chunk (deterministic reduce)
__device__ float g_partial[NCHUNK][BB * DD];   // 8 MB static scratch

// ---------------------------------------------------------------------------
// Kernel 1: scores[b,m] = softmax_m( dot(x[b,:], W[m,:]) + bias[m] )
// (unchanged from R5 — correct, ~30us incl. overheads; fused kernel is the
//  dominant cost this round)
// ---------------------------------------------------------------------------
__global__ __launch_bounds__(256)
void poly_scores_kernel(const float* __restrict__ x,
                        const float* __restrict__ W,
                        const float* __restrict__ bias,
                        float* __restrict__ scores)
{
    __shared__ float4 xs[RB * (DD / 4)];       // 16 KB
    __shared__ float  logits[RB][MM];          // 8 KB

    const int b0 = blockIdx.x * RB;
    const int t  = threadIdx.x;                // 0..255 == mode index

    const float4* x4 = reinterpret_cast<const float4*>(x + (size_t)b0 * DD);
    #pragma unroll
    for (int i = t; i < RB * (DD / 4); i += 256) xs[i] = x4[i];
    __syncthreads();

    float acc[RB];
    #pragma unroll
    for (int r = 0; r < RB; ++r) acc[r] = 0.0f;

    const float4* w4 = reinterpret_cast<const float4*>(W + (size_t)t * DD);
    #pragma unroll 4
    for (int k = 0; k < DD / 4; ++k) {
        float4 wv = w4[k];
        #pragma unroll
        for (int r = 0; r < RB; ++r) {
            float4 xv = xs[r * (DD / 4) + k];
            acc[r] = fmaf(wv.x, xv.x, acc[r]);
            acc[r] = fmaf(wv.y, xv.y, acc[r]);
            acc[r] = fmaf(wv.z, xv.z, acc[r]);
            acc[r] = fmaf(wv.w, xv.w, acc[r]);
        }
    }
    const float bv = bias[t];
    #pragma unroll
    for (int r = 0; r < RB; ++r) logits[r][t] = acc[r] + bv;
    __syncthreads();

    const int w    = t >> 5;
    const int lane = t & 31;
    float v[8];
    float mx = -1e30f;
    #pragma unroll
    for (int j = 0; j < 8; ++j) { v[j] = logits[w][lane + 32 * j]; mx = fmaxf(mx, v[j]); }
    #pragma unroll
    for (int o = 16; o > 0; o >>= 1) mx = fmaxf(mx, __shfl_xor_sync(0xFFFFFFFFu, mx, o));
    float s = 0.0f;
    #pragma unroll
    for (int j = 0; j < 8; ++j) { v[j] = __expf(v[j] - mx); s += v[j]; }
    #pragma unroll
    for (int o = 16; o > 0; o >>= 1) s += __shfl_xor_sync(0xFFFFFFFFu, s, o);
    const float inv = 1.0f / s;

    float* srow = scores + (size_t)(b0 + w) * MM;
    #pragma unroll
    for (int j = 0; j < 8; ++j) srow[lane + 32 * j] = v[j] * inv;
}

// ---------------------------------------------------------------------------
// Kernel 2: grid (1024 b, 4 mode-chunks) x 128 threads.
// Each block streams 64 modes for one batch row; accumulates a PARTIAL mixed
// into g_partial[chunk]. 4096 blocks -> ~11 blocks/SM -> ~70-75% occupancy
// (vs 41% before), raising outstanding-load count to saturate HBM.
// ---------------------------------------------------------------------------
__global__ __launch_bounds__(128)
void poly_fused_chunk_kernel(const float* __restrict__ x,
                             const float* __restrict__ mem,
                             const float* __restrict__ scores,
                             float* __restrict__ mem_new)
{
    __shared__ float s_sc[MCH];

    const int b  = blockIdx.x;
    const int c  = blockIdx.y;
    const int m0 = c * MCH;
    const int t  = threadIdx.x;                // 0..127 (float4 lane over D)

    if (t < MCH) s_sc[t] = scores[(size_t)b * MM + m0 + t];
    __syncthreads();

    const size_t base = (size_t)b * (DD / 4) + t;   // in float4 units
    const float4 xv   = reinterpret_cast<const float4*>(x)[base];

    const float4* m4 = reinterpret_cast<const float4*>(mem);
    float4*       o4 = reinterpret_cast<float4*>(mem_new);

    float4 acc = make_float4(0.f, 0.f, 0.f, 0.f);
    const size_t stride = (size_t)(BB * DD / 4);    // float4 per mode

    #pragma unroll 8
    for (int mi = 0; mi < MCH; ++mi) {
        const int    m   = m0 + mi;
        const size_t idx = base + (size_t)m * stride;
        const float4 mv  = __ldcs(m4 + idx);        // streaming, no reuse
        const float beta = (float)m / 257.0f;

        float4 mn;
        mn.x = fmaf(beta, mv.x, xv.x) - (mv.x > THRESHV ? 1.0f : 0.0f);
        mn.y = fmaf(beta, mv.y, xv.y) - (mv.y > THRESHV ? 1.0f : 0.0f);
        mn.z = fmaf(beta, mv.z, xv.z) - (mv.z > THRESHV ? 1.0f : 0.0f);
        mn.w = fmaf(beta, mv.w, xv.w) - (mv.w > THRESHV ? 1.0f : 0.0f);

        __stcs(o4 + idx, mn);

        const float sc = s_sc[mi];
        acc.x += (mn.x - THRESHV > 0.0f) ? sc : 0.0f;
        acc.y += (mn.y - THRESHV > 0.0f) ? sc : 0.0f;
        acc.z += (mn.z - THRESHV > 0.0f) ? sc : 0.0f;
        acc.w += (mn.w - THRESHV > 0.0f) ? sc : 0.0f;
    }

    reinterpret_cast<float4*>(&g_partial[c][0])[base] = acc;
}

// ---------------------------------------------------------------------------
// Kernel 3: mixed = sum over the 4 chunk partials. 18 MB traffic, ~2-3us.
// ---------------------------------------------------------------------------
__global__ __launch_bounds__(256)
void poly_reduce_kernel(float* __restrict__ mixed)
{
    const size_t i = (size_t)blockIdx.x * 256 + threadIdx.x;  // float4 index
    const float4 p0 = reinterpret_cast<const float4*>(&g_partial[0][0])[i];
    const float4 p1 = reinterpret_cast<const float4*>(&g_partial[1][0])[i];
    const float4 p2 = reinterpret_cast<const float4*>(&g_partial[2][0])[i];
    const float4 p3 = reinterpret_cast<const float4*>(&g_partial[3][0])[i];
    float4 r;
    r.x = (p0.x + p1.x) + (p2.x + p3.x);
    r.y = (p0.y + p1.y) + (p2.y + p3.y);
    r.z = (p0.z + p1.z) + (p2.z + p3.z);
    r.w = (p0.w + p1.w) + (p2.w + p3.w);
    reinterpret_cast<float4*>(mixed)[i] = r;
}

// ---------------------------------------------------------------------------
// Launch: outputs packed as [mixed (B*D) | mem_new (M*B*D) | scores (B*M)]
// ---------------------------------------------------------------------------
extern "C" void kernel_launch(void* const* d_in, const int* in_sizes, int n_in,
                              void* d_out, int out_size)
{
    const float* x    = (const float*)d_in[0];   // [B, D]
    const float* mem  = (const float*)d_in[1];   // [M, B, D]
    const float* W    = (const float*)d_in[2];   // [M, D]
    const float* bias = (const float*)d_in[3];   // [M]

    float* out     = (float*)d_out;
    float* mixed   = out;                                          // B*D
    float* mem_new = out + (size_t)BB * DD;                        // M*B*D
    float* scores  = out + (size_t)BB * DD + (size_t)MM * BB * DD; // B*M

    poly_scores_kernel<<<BB / RB, 256>>>(x, W, bias, scores);
    poly_fused_chunk_kernel<<<dim3(BB, NCHUNK), 128>>>(x, mem, scores, mem_new);
    poly_reduce_kernel<<<(BB * DD / 4) / 256, 256>>>(mixed);
}